// round 14
// baseline (speedup 1.0000x reference)
#include <cuda_runtime.h>

#define BATCH 16
#define NNODE 32
#define DEG 64
#define KNN 8
#define IN_F 128
#define OUT_F 3
#define NPTS 2048   // NNODE*DEG
#define JCOLS 8192  // DEG*IN_F

typedef unsigned long long ull;

// ---------- device scratch (no allocations allowed) ----------
__device__ float  g_root[BATCH * NNODE * OUT_F];
__device__ float  g_Wl[IN_F * OUT_F];     // collapsed Wl1@Wl2, layout [f*3+o]
__device__ float  g_ceff[OUT_F * 6];      // collapsed c2w@c1w, layout [p*6+c]
__device__ float  g_beff[OUT_F];          // c2w@c1b + c2b
__device__ float4 g_x[BATCH * NPTS];      // (x0,x1,x2, 0.5*||x||^2)

// ---------- packed f32x2 helpers ----------
__device__ __forceinline__ ull splat2(float w) {
    ull r;
    asm("mov.b64 %0, {%1, %1};" : "=l"(r) : "f"(w));
    return r;
}
__device__ __forceinline__ void ffma2(ull& d, ull a, ull b) {
    asm("fma.rn.f32x2 %0, %1, %2, %0;" : "+l"(d) : "l"(a), "l"(b));
}
__device__ __forceinline__ ull ffma2r(ull a, ull b, ull c) {
    ull d;
    asm("fma.rn.f32x2 %0, %1, %2, %3;" : "=l"(d) : "l"(a), "l"(b), "l"(c));
    return d;
}
__device__ __forceinline__ ull add2r(ull a, ull b) {
    ull d;
    asm("add.rn.f32x2 %0, %1, %2;" : "=l"(d) : "l"(a), "l"(b));
    return d;
}
__device__ __forceinline__ float lo2(ull v) {
    return __uint_as_float((unsigned)(v & 0xffffffffu));
}
__device__ __forceinline__ float hi2(ull v) {
    return __uint_as_float((unsigned)(v >> 32));
}

__device__ __forceinline__ float wredsum(float v) {
    #pragma unroll
    for (int o = 16; o > 0; o >>= 1) v += __shfl_xor_sync(0xffffffffu, v, o);
    return v;
}

// ---------- profiling probes: keep ncu capture landing on k1 ----------
__global__ void k_probe1() {}
__global__ void k_probe2() {}

// ============================================================
// K0: parallel prep (unchanged — measured ~9.7us).
// ============================================================
__global__ __launch_bounds__(128) void k0_prep(
        const float* __restrict__ t0, const float* __restrict__ t1,
        const float* __restrict__ t2, const float* __restrict__ t3,
        const float* __restrict__ t4, const float* __restrict__ t5,
        const float* __restrict__ Wr0, const float* __restrict__ Wr1,
        const float* __restrict__ Wr2, const float* __restrict__ Wr3,
        const float* __restrict__ Wr4, const float* __restrict__ Wr5,
        const float* __restrict__ Wl1, const float* __restrict__ Wl2,
        const float* __restrict__ c1w, const float* __restrict__ c1b,
        const float* __restrict__ c2w, const float* __restrict__ c2b) {
    const int bid = blockIdx.x;
    const int tid = threadIdx.x;
    const int w   = tid >> 5, lane = tid & 31;
    __shared__ float red[4][3];

    if (bid < 512) {
        const int b = bid >> 5, n = bid & 31;
        float s0 = 0.f, s1 = 0.f, s2 = 0.f;
        for (int idx = tid; idx < 1120; idx += 128) {
            float v; const float* wp;
            if (idx < 96) {
                v = t0[b * 96 + idx];                           wp = Wr0 + idx * 3;
            } else if (idx < 352) {
                int i = idx - 96;
                v = t1[(b * 2  + (n >> 4)) * 256 + i];          wp = Wr1 + i * 3;
            } else if (idx < 608) {
                int i = idx - 352;
                v = t2[(b * 4  + (n >> 3)) * 256 + i];          wp = Wr2 + i * 3;
            } else if (idx < 864) {
                int i = idx - 608;
                v = t3[(b * 8  + (n >> 2)) * 256 + i];          wp = Wr3 + i * 3;
            } else if (idx < 992) {
                int i = idx - 864;
                v = t4[(b * 16 + (n >> 1)) * 128 + i];          wp = Wr4 + i * 3;
            } else {
                int i = idx - 992;
                v = t5[(b * 32 +  n      ) * 128 + i];          wp = Wr5 + i * 3;
            }
            s0 = fmaf(v, wp[0], s0); s1 = fmaf(v, wp[1], s1); s2 = fmaf(v, wp[2], s2);
        }
        s0 = wredsum(s0); s1 = wredsum(s1); s2 = wredsum(s2);
        if (lane == 0) { red[w][0] = s0; red[w][1] = s1; red[w][2] = s2; }
        __syncthreads();
        if (tid < 3)
            g_root[(b * NNODE + n) * 3 + tid] =
                red[0][tid] + red[1][tid] + red[2][tid] + red[3][tid];
    } else if (bid < 640) {
        const int f = bid - 512;
        float s0 = 0.f, s1 = 0.f, s2 = 0.f;
        for (int tt = tid; tt < 1280; tt += 128) {
            float v = Wl1[f * 1280 + tt];
            s0 = fmaf(v, Wl2[tt * 3 + 0], s0);
            s1 = fmaf(v, Wl2[tt * 3 + 1], s1);
            s2 = fmaf(v, Wl2[tt * 3 + 2], s2);
        }
        s0 = wredsum(s0); s1 = wredsum(s1); s2 = wredsum(s2);
        if (lane == 0) { red[w][0] = s0; red[w][1] = s1; red[w][2] = s2; }
        __syncthreads();
        if (tid < 3)
            g_Wl[f * 3 + tid] =
                red[0][tid] + red[1][tid] + red[2][tid] + red[3][tid];
    } else {
        if (tid < 18) {
            int p = tid / 6, c = tid % 6;
            float s = 0.f;
            for (int o = 0; o < 64; o++) s = fmaf(c2w[p * 64 + o], c1w[o * 6 + c], s);
            g_ceff[tid] = s;
        } else if (tid < 21) {
            int p = tid - 18;
            float s = c2b[p];
            for (int o = 0; o < 64; o++) s = fmaf(c2w[p * 64 + o], c1b[o], s);
            g_beff[p] = s;
        }
    }
}

// ============================================================
// K1: smeared-load pipeline. Loads for window w+1 are interleaved
// one-per-i INSIDE the compute of window w (instead of an 8-LDG
// front burst): same MLP (dist-1, 8 outstanding), but LDGs spaced
// ~26 instrs apart -> shallow L1tex queue (B300 MLP_p1 contention).
// ============================================================
#define K1_STEP(bufC, bufN, wc, wn, DO_LOAD)                          \
    {                                                                 \
        _Pragma("unroll")                                             \
        for (int k = 0; k < 8; k++) {                                 \
            if (DO_LOAD)                                              \
                bufN[k] = __ldcs(wptr + (size_t)((wn) * 8 + k) * (JCOLS / 2)); \
            ull w0 = splat2(bufC[k].x), w1 = splat2(bufC[k].y);       \
            const ulonglong2* sap =                                   \
                (const ulonglong2*)(sa + ((wc) * 8 + k) * 8);         \
            _Pragma("unroll")                                         \
            for (int q = 0; q < 4; q++) {                             \
                ulonglong2 ap = sap[q];                               \
                ffma2(acc[0][2 * q],     ap.x, w0);                   \
                ffma2(acc[1][2 * q],     ap.x, w1);                   \
                ffma2(acc[0][2 * q + 1], ap.y, w0);                   \
                ffma2(acc[1][2 * q + 1], ap.y, w1);                   \
            }                                                         \
        }                                                             \
    }

__global__ __launch_bounds__(256, 3) void k1_branch(const float* __restrict__ t5,
                                                    const float* __restrict__ Wb) {
    const int n   = blockIdx.x >> 4;
    const int jt  = blockIdx.x & 15;
    const int j0  = jt * 512;
    const int tid = threadIdx.x;

    __shared__ __align__(16) ull sa[IN_F * 8];  // [i][bpair]
    __shared__ __align__(8) float sC[16][516];
    __shared__ float sWl[IN_F * OUT_F];

    {
        int i = tid & 127, ph = (tid >> 7) * 4;
        #pragma unroll
        for (int pp = 0; pp < 4; pp++) {
            int p = ph + pp;
            float a0 = t5[((2 * p)     * NNODE + n) * IN_F + i];
            float a1 = t5[((2 * p + 1) * NNODE + n) * IN_F + i];
            sa[i * 8 + p] = ((ull)__float_as_uint(a1) << 32)
                          | (ull)__float_as_uint(a0);
        }
        for (int q = tid; q < IN_F * OUT_F; q += 256) sWl[q] = g_Wl[q];
    }
    __syncthreads();

    ull acc[2][8];
    #pragma unroll
    for (int c = 0; c < 2; c++)
        #pragma unroll
        for (int p = 0; p < 8; p++) acc[c][p] = 0ull;

    const float2* wptr =
        (const float2*)(Wb + (size_t)n * IN_F * JCOLS + j0 + 2 * tid);

    float2 bufA[8], bufB[8];
    {   // prologue: window 0 in flight (one unavoidable burst)
        #pragma unroll
        for (int k = 0; k < 8; k++)
            bufA[k] = __ldcs(wptr + (size_t)k * (JCOLS / 2));
    }

    #pragma unroll 1
    for (int ii = 0; ii < 14; ii += 2) {
        K1_STEP(bufA, bufB, ii,     ii + 1, true);
        K1_STEP(bufB, bufA, ii + 1, ii + 2, true);
    }
    K1_STEP(bufA, bufB, 14, 15, true);
    K1_STEP(bufB, bufA, 15, 15, false);

    #pragma unroll
    for (int p = 0; p < 8; p++) {
        float l0 = lo2(acc[0][p]), h0 = hi2(acc[0][p]);
        float l1 = lo2(acc[1][p]), h1 = hi2(acc[1][p]);
        l0 = l0 >= 0.f ? l0 : 0.2f * l0;
        h0 = h0 >= 0.f ? h0 : 0.2f * h0;
        l1 = l1 >= 0.f ? l1 : 0.2f * l1;
        h1 = h1 >= 0.f ? h1 : 0.2f * h1;
        *(float2*)&sC[2 * p][2 * tid]     = make_float2(l0, l1);
        *(float2*)&sC[2 * p + 1][2 * tid] = make_float2(h0, h1);
    }
    __syncthreads();

    if (tid < 64) {
        int d = tid >> 4, b = tid & 15;
        float s0 = 0.f, s1 = 0.f, s2 = 0.f;
        const float* row = &sC[b][d * 128];
        #pragma unroll 4
        for (int f = 0; f < 128; f++) {
            float cv = row[f];
            s0 = fmaf(cv, sWl[f * 3 + 0], s0);
            s1 = fmaf(cv, sWl[f * 3 + 1], s1);
            s2 = fmaf(cv, sWl[f * 3 + 2], s2);
        }
        const float* rp = &g_root[(b * NNODE + n) * 3];
        float x0 = s0 + rp[0], x1 = s1 + rp[1], x2 = s2 + rp[2];
        float hxx = 0.5f * (x0 * x0 + x1 * x1 + x2 * x2);
        int dglob = jt * 4 + d;
        g_x[b * NPTS + n * DEG + dglob] = make_float4(x0, x1, x2, hxx);
    }
}

// ============================================================
// K2: node-bound pruned kNN (R13 structure) + parallel prepass
// (2 threads/node, stagger-indexed, shfl-combined; radius uses the
// SAME centroid both halves -> bound validity unchanged).
// ============================================================
__device__ __forceinline__ void topk_ins(float v, int m, float* val, int* idx) {
    float cv = v; int ci = m;
    #pragma unroll
    for (int s = 0; s < KNN; s++) {
        bool gt = (cv > val[s]) || (cv == val[s] && ci < idx[s]);
        float ov = val[s]; int oi = idx[s];
        val[s] = gt ? cv : ov;
        idx[s] = gt ? ci : oi;
        cv = gt ? ov : cv;
        ci = gt ? oi : ci;
    }
}

__global__ __launch_bounds__(64) void k2_knn(const float* __restrict__ bias,
                                             float* __restrict__ out) {
    const int b    = blockIdx.x >> 5;    // 16 batches x 32 nodes (chunks of 64)
    const int chnk = blockIdx.x & 31;
    const int tid  = threadIdx.x;

    __shared__ __align__(16) float sX[NPTS], sY[NPTS], sZ[NPTS], sW[NPTS];
    __shared__ float scx[NNODE], scy[NNODE], scz[NNODE], srad[NNODE];
    __shared__ float sce[18], sbe[3];
    #pragma unroll
    for (int q = 0; q < NPTS / 64; q++) {
        int i = q * 64 + tid;
        float4 v = g_x[b * NPTS + i];
        sX[i] = v.x; sY[i] = v.y; sZ[i] = v.z; sW[i] = -v.w;
    }
    if (tid < 18) sce[tid] = g_ceff[tid];
    if (tid < 3)  sbe[tid] = g_beff[tid];
    __syncthreads();

    // ---- prepass: 2 threads per node (halves combined via shfl) ----
    {
        const int node = tid >> 1, half = tid & 1;
        float cx = 0.f, cy = 0.f, cz = 0.f;
        #pragma unroll 4
        for (int j = 0; j < 32; j++) {
            int e = (j + node + half * 16) & 31;        // bank-staggered
            int i = node * DEG + half * 32 + e;
            cx += sX[i]; cy += sY[i]; cz += sZ[i];
        }
        cx += __shfl_xor_sync(0xffffffffu, cx, 1);
        cy += __shfl_xor_sync(0xffffffffu, cy, 1);
        cz += __shfl_xor_sync(0xffffffffu, cz, 1);
        cx *= (1.f / DEG); cy *= (1.f / DEG); cz *= (1.f / DEG);
        float r2 = 0.f;
        #pragma unroll 4
        for (int j = 0; j < 32; j++) {
            int e = (j + node + half * 16) & 31;
            int i = node * DEG + half * 32 + e;
            float dx = sX[i] - cx, dy = sY[i] - cy, dz = sZ[i] - cz;
            r2 = fmaxf(r2, dx * dx + dy * dy + dz * dz);
        }
        r2 = fmaxf(r2, __shfl_xor_sync(0xffffffffu, r2, 1));
        if (half == 0) {
            scx[node] = cx; scy[node] = cy; scz[node] = cz;
            srad[node] = sqrtf(r2) * 1.0001f + 1e-5f;   // inflated (conservative)
        }
    }
    __syncthreads();

    const int n = chnk * 64 + tid;       // this thread's point
    const float nx = sX[n], ny = sY[n], nz = sZ[n];
    const ull nx2 = splat2(nx), ny2 = splat2(ny), nz2 = splat2(nz);
    const ull c0  = splat2(sW[n]);       // = -0.5*||xn||^2

    float val[KNN]; int idx[KNN];
    #pragma unroll
    for (int k = 0; k < KNN; k++) { val[k] = -3.4e38f; idx[k] = 0x7fffffff; }

    const ulonglong2* pX = (const ulonglong2*)sX;
    const ulonglong2* pY = (const ulonglong2*)sY;
    const ulonglong2* pZ = (const ulonglong2*)sZ;
    const ulonglong2* pW = (const ulonglong2*)sW;

    #define K2_SCAN_GROUP(gg)                                                  \
    {                                                                          \
        const int m0 = (gg) * 8;                                               \
        ulonglong2 cX = pX[2 * (gg)],     cY = pY[2 * (gg)],                   \
                   cZ = pZ[2 * (gg)],     cW = pW[2 * (gg)];                   \
        ulonglong2 dX = pX[2 * (gg) + 1], dY = pY[2 * (gg) + 1],               \
                   dZ = pZ[2 * (gg) + 1], dW = pW[2 * (gg) + 1];               \
        ull t0 = ffma2r(nx2, cX.x, ffma2r(ny2, cY.x, ffma2r(nz2, cZ.x, add2r(c0, cW.x)))); \
        ull t1 = ffma2r(nx2, cX.y, ffma2r(ny2, cY.y, ffma2r(nz2, cZ.y, add2r(c0, cW.y)))); \
        ull t2 = ffma2r(nx2, dX.x, ffma2r(ny2, dY.x, ffma2r(nz2, dZ.x, add2r(c0, dW.x)))); \
        ull t3 = ffma2r(nx2, dX.y, ffma2r(ny2, dY.y, ffma2r(nz2, dZ.y, add2r(c0, dW.y)))); \
        float s0 = lo2(t0), s1 = hi2(t0), s2 = lo2(t1), s3 = hi2(t1);          \
        float s4 = lo2(t2), s5 = hi2(t2), s6 = lo2(t3), s7 = hi2(t3);          \
        float gm = fmaxf(fmaxf(fmaxf(s0, s1), fmaxf(s2, s3)),                  \
                         fmaxf(fmaxf(s4, s5), fmaxf(s6, s7)));                 \
        if (gm >= val[KNN - 1]) {                                              \
            if (s0 >= val[KNN - 1]) topk_ins(s0, m0 + 0, val, idx);            \
            if (s1 >= val[KNN - 1]) topk_ins(s1, m0 + 1, val, idx);            \
            if (s2 >= val[KNN - 1]) topk_ins(s2, m0 + 2, val, idx);            \
            if (s3 >= val[KNN - 1]) topk_ins(s3, m0 + 3, val, idx);            \
            if (s4 >= val[KNN - 1]) topk_ins(s4, m0 + 4, val, idx);            \
            if (s5 >= val[KNN - 1]) topk_ins(s5, m0 + 5, val, idx);            \
            if (s6 >= val[KNN - 1]) topk_ins(s6, m0 + 6, val, idx);            \
            if (s7 >= val[KNN - 1]) topk_ins(s7, m0 + 7, val, idx);            \
        }                                                                      \
    }

    // ---- warm-up: own node's 64 candidates (8 groups) ----
    #pragma unroll 1
    for (int t = 0; t < 8; t++) {
        K2_SCAN_GROUP(chnk * 8 + t);
    }

    // ---- prune: search radius from the 8th-best own-node score ----
    const float tau = val[KNN - 1];                   // = -0.5*d8^2 (<= 0)
    const float srch = sqrtf(fmaxf(-2.f * tau, 0.f)) * 1.0001f + 1e-5f;

    #pragma unroll 1
    for (int mn = 0; mn < NNODE; mn++) {
        if (mn == chnk) continue;
        float dx = nx - scx[mn], dy = ny - scy[mn], dz = nz - scz[mn];
        float d2  = dx * dx + dy * dy + dz * dz;
        float rhs = srad[mn] + srch;
        if (d2 <= rhs * rhs) {                        // node may contain a top-8
            #pragma unroll 1
            for (int t = 0; t < 8; t++) {
                K2_SCAN_GROUP(mn * 8 + t);
            }
        }
    }
    #undef K2_SCAN_GROUP

    float h0 = -3.4e38f, h1 = -3.4e38f, h2 = -3.4e38f;
    #pragma unroll
    for (int k = 0; k < KNN; k++) {
        int m = idx[k];
        float mx = sX[m], my = sY[m], mz = sZ[m];
        float g0f = mx - nx, g1f = my - ny, g2f = mz - nz;
        float u0 = sbe[0] + sce[0]  * g0f + sce[1]  * g1f + sce[2]  * g2f
                          + sce[3]  * nx + sce[4]  * ny + sce[5]  * nz;
        float u1 = sbe[1] + sce[6]  * g0f + sce[7]  * g1f + sce[8]  * g2f
                          + sce[9]  * nx + sce[10] * ny + sce[11] * nz;
        float u2 = sbe[2] + sce[12] * g0f + sce[13] * g1f + sce[14] * g2f
                          + sce[15] * nx + sce[16] * ny + sce[17] * nz;
        h0 = fmaxf(h0, u0); h1 = fmaxf(h1, u1); h2 = fmaxf(h2, u2);
    }

    const int bq = tid * 3;              // bias tiled with period DEG=64; n&63==tid
    float o0 = h0 + bias[bq + 0];
    float o1 = h1 + bias[bq + 1];
    float o2 = h2 + bias[bq + 2];
    o0 = o0 >= 0.f ? o0 : 0.2f * o0;
    o1 = o1 >= 0.f ? o1 : 0.2f * o1;
    o2 = o2 >= 0.f ? o2 : 0.2f * o2;

    float* op = out + (size_t)(b * NPTS + n) * 3;
    op[0] = o0; op[1] = o1; op[2] = o2;
}

// ============================================================
extern "C" void kernel_launch(void* const* d_in, const int* in_sizes, int n_in,
                              void* d_out, int out_size) {
    const float* t0  = (const float*)d_in[0];
    const float* t1  = (const float*)d_in[1];
    const float* t2  = (const float*)d_in[2];
    const float* t3  = (const float*)d_in[3];
    const float* t4  = (const float*)d_in[4];
    const float* t5  = (const float*)d_in[5];
    const float* Wr0 = (const float*)d_in[6];
    const float* Wr1 = (const float*)d_in[7];
    const float* Wr2 = (const float*)d_in[8];
    const float* Wr3 = (const float*)d_in[9];
    const float* Wr4 = (const float*)d_in[10];
    const float* Wr5 = (const float*)d_in[11];
    const float* Wb  = (const float*)d_in[12];
    const float* Wl1 = (const float*)d_in[13];
    const float* Wl2 = (const float*)d_in[14];
    const float* bia = (const float*)d_in[15];
    const float* c1w = (const float*)d_in[16];
    const float* c1b = (const float*)d_in[17];
    const float* c2w = (const float*)d_in[18];
    const float* c2b = (const float*)d_in[19];

    k_probe1<<<1, 32>>>();   // keep ncu capture window on k1
    k_probe2<<<1, 32>>>();
    k0_prep<<<641, 128>>>(t0, t1, t2, t3, t4, t5,
                          Wr0, Wr1, Wr2, Wr3, Wr4, Wr5,
                          Wl1, Wl2, c1w, c1b, c2w, c2b);
    k1_branch<<<NNODE * 16, 256>>>(t5, Wb);
    k2_knn<<<BATCH * 32, 64>>>(bia, (float*)d_out);
}

// round 15
// speedup vs baseline: 1.0797x; 1.0797x over previous
#include <cuda_runtime.h>

#define BATCH 16
#define NNODE 32
#define DEG 64
#define KNN 8
#define IN_F 128
#define OUT_F 3
#define NPTS 2048   // NNODE*DEG
#define JCOLS 8192  // DEG*IN_F

typedef unsigned long long ull;

// ---------- device scratch (no allocations allowed) ----------
__device__ float  g_root[BATCH * NNODE * OUT_F];
__device__ float  g_Wl[IN_F * OUT_F];     // collapsed Wl1@Wl2, layout [f*3+o]
__device__ float  g_ceff[OUT_F * 6];      // collapsed c2w@c1w, layout [p*6+c]
__device__ float  g_beff[OUT_F];          // c2w@c1b + c2b
__device__ float4 g_x[BATCH * NPTS];      // (x0,x1,x2, 0.5*||x||^2)

// ---------- packed f32x2 helpers ----------
__device__ __forceinline__ ull splat2(float w) {
    ull r;
    asm("mov.b64 %0, {%1, %1};" : "=l"(r) : "f"(w));
    return r;
}
__device__ __forceinline__ void ffma2(ull& d, ull a, ull b) {
    asm("fma.rn.f32x2 %0, %1, %2, %0;" : "+l"(d) : "l"(a), "l"(b));
}
__device__ __forceinline__ ull ffma2r(ull a, ull b, ull c) {
    ull d;
    asm("fma.rn.f32x2 %0, %1, %2, %3;" : "=l"(d) : "l"(a), "l"(b), "l"(c));
    return d;
}
__device__ __forceinline__ ull add2r(ull a, ull b) {
    ull d;
    asm("add.rn.f32x2 %0, %1, %2;" : "=l"(d) : "l"(a), "l"(b));
    return d;
}
__device__ __forceinline__ float lo2(ull v) {
    return __uint_as_float((unsigned)(v & 0xffffffffu));
}
__device__ __forceinline__ float hi2(ull v) {
    return __uint_as_float((unsigned)(v >> 32));
}

__device__ __forceinline__ float wredsum(float v) {
    #pragma unroll
    for (int o = 16; o > 0; o >>= 1) v += __shfl_xor_sync(0xffffffffu, v, o);
    return v;
}

// ============================================================
// K0: prep with 256-thread blocks -> 5 strided iterations (loads
// batch under unroll: MLP~5 instead of a 9-10 deep serial chain).
// ============================================================
__global__ __launch_bounds__(256) void k0_prep(
        const float* __restrict__ t0, const float* __restrict__ t1,
        const float* __restrict__ t2, const float* __restrict__ t3,
        const float* __restrict__ t4, const float* __restrict__ t5,
        const float* __restrict__ Wr0, const float* __restrict__ Wr1,
        const float* __restrict__ Wr2, const float* __restrict__ Wr3,
        const float* __restrict__ Wr4, const float* __restrict__ Wr5,
        const float* __restrict__ Wl1, const float* __restrict__ Wl2,
        const float* __restrict__ c1w, const float* __restrict__ c1b,
        const float* __restrict__ c2w, const float* __restrict__ c2b) {
    const int bid = blockIdx.x;
    const int tid = threadIdx.x;
    const int w   = tid >> 5, lane = tid & 31;
    __shared__ float red[8][3];

    if (bid < 512) {
        const int b = bid >> 5, n = bid & 31;
        float s0 = 0.f, s1 = 0.f, s2 = 0.f;
        #pragma unroll
        for (int it = 0; it < 5; it++) {
            int idx = tid + it * 256;
            if (idx < 1120) {
                float v; const float* wp;
                if (idx < 96) {
                    v = t0[b * 96 + idx];                           wp = Wr0 + idx * 3;
                } else if (idx < 352) {
                    int i = idx - 96;
                    v = t1[(b * 2  + (n >> 4)) * 256 + i];          wp = Wr1 + i * 3;
                } else if (idx < 608) {
                    int i = idx - 352;
                    v = t2[(b * 4  + (n >> 3)) * 256 + i];          wp = Wr2 + i * 3;
                } else if (idx < 864) {
                    int i = idx - 608;
                    v = t3[(b * 8  + (n >> 2)) * 256 + i];          wp = Wr3 + i * 3;
                } else if (idx < 992) {
                    int i = idx - 864;
                    v = t4[(b * 16 + (n >> 1)) * 128 + i];          wp = Wr4 + i * 3;
                } else {
                    int i = idx - 992;
                    v = t5[(b * 32 +  n      ) * 128 + i];          wp = Wr5 + i * 3;
                }
                s0 = fmaf(v, wp[0], s0); s1 = fmaf(v, wp[1], s1); s2 = fmaf(v, wp[2], s2);
            }
        }
        s0 = wredsum(s0); s1 = wredsum(s1); s2 = wredsum(s2);
        if (lane == 0) { red[w][0] = s0; red[w][1] = s1; red[w][2] = s2; }
        __syncthreads();
        if (tid < 3) {
            float t = 0.f;
            #pragma unroll
            for (int q = 0; q < 8; q++) t += red[q][tid];
            g_root[(b * NNODE + n) * 3 + tid] = t;
        }
    } else if (bid < 640) {
        const int f = bid - 512;
        float s0 = 0.f, s1 = 0.f, s2 = 0.f;
        #pragma unroll
        for (int it = 0; it < 5; it++) {
            int tt = tid + it * 256;   // 1280 = 5*256 exactly
            float v = Wl1[f * 1280 + tt];
            s0 = fmaf(v, Wl2[tt * 3 + 0], s0);
            s1 = fmaf(v, Wl2[tt * 3 + 1], s1);
            s2 = fmaf(v, Wl2[tt * 3 + 2], s2);
        }
        s0 = wredsum(s0); s1 = wredsum(s1); s2 = wredsum(s2);
        if (lane == 0) { red[w][0] = s0; red[w][1] = s1; red[w][2] = s2; }
        __syncthreads();
        if (tid < 3) {
            float t = 0.f;
            #pragma unroll
            for (int q = 0; q < 8; q++) t += red[q][tid];
            g_Wl[f * 3 + tid] = t;
        }
    } else {
        if (tid < 18) {
            int p = tid / 6, c = tid % 6;
            float s = 0.f;
            for (int o = 0; o < 64; o++) s = fmaf(c2w[p * 64 + o], c1w[o * 6 + c], s);
            g_ceff[tid] = s;
        } else if (tid < 21) {
            int p = tid - 18;
            float s = c2b[p];
            for (int o = 0; o < 64; o++) s = fmaf(c2w[p * 64 + o], c1b[o], s);
            g_beff[p] = s;
        }
    }
}

// ============================================================
// K1: EXACT R11 version (best measured: 44.1us; R12/R14 variants
// both regressed). Window-8 distance-1 pipeline, two named buffers.
// ============================================================
#define K1_LOAD(buf, wi)                                              \
    {                                                                 \
        _Pragma("unroll")                                             \
        for (int k = 0; k < 8; k++)                                   \
            buf[k] = __ldcs(wptr + (size_t)((wi) * 8 + k) * (JCOLS / 2)); \
    }

#define K1_COMPUTE(buf, wi)                                           \
    {                                                                 \
        _Pragma("unroll")                                             \
        for (int k = 0; k < 8; k++) {                                 \
            ull w0 = splat2(buf[k].x), w1 = splat2(buf[k].y);         \
            const ulonglong2* sap =                                   \
                (const ulonglong2*)(sa + ((wi) * 8 + k) * 8);         \
            _Pragma("unroll")                                         \
            for (int q = 0; q < 4; q++) {                             \
                ulonglong2 ap = sap[q];                               \
                ffma2(acc[0][2 * q],     ap.x, w0);                   \
                ffma2(acc[1][2 * q],     ap.x, w1);                   \
                ffma2(acc[0][2 * q + 1], ap.y, w0);                   \
                ffma2(acc[1][2 * q + 1], ap.y, w1);                   \
            }                                                         \
        }                                                             \
    }

__global__ __launch_bounds__(256, 3) void k1_branch(const float* __restrict__ t5,
                                                    const float* __restrict__ Wb) {
    const int n   = blockIdx.x >> 4;
    const int jt  = blockIdx.x & 15;
    const int j0  = jt * 512;
    const int tid = threadIdx.x;

    __shared__ __align__(16) ull sa[IN_F * 8];  // [i][bpair]
    __shared__ __align__(8) float sC[16][516];
    __shared__ float sWl[IN_F * OUT_F];

    {
        int i = tid & 127, ph = (tid >> 7) * 4;
        #pragma unroll
        for (int pp = 0; pp < 4; pp++) {
            int p = ph + pp;
            float a0 = t5[((2 * p)     * NNODE + n) * IN_F + i];
            float a1 = t5[((2 * p + 1) * NNODE + n) * IN_F + i];
            sa[i * 8 + p] = ((ull)__float_as_uint(a1) << 32)
                          | (ull)__float_as_uint(a0);
        }
        for (int q = tid; q < IN_F * OUT_F; q += 256) sWl[q] = g_Wl[q];
    }
    __syncthreads();

    ull acc[2][8];
    #pragma unroll
    for (int c = 0; c < 2; c++)
        #pragma unroll
        for (int p = 0; p < 8; p++) acc[c][p] = 0ull;

    const float2* wptr =
        (const float2*)(Wb + (size_t)n * IN_F * JCOLS + j0 + 2 * tid);

    float2 bufA[8], bufB[8];
    K1_LOAD(bufA, 0);                    // prologue: window 0 in flight

    #pragma unroll 1
    for (int ii = 0; ii < 16; ii += 2) {
        K1_LOAD(bufB, ii + 1);           // next window in flight...
        K1_COMPUTE(bufA, ii);            // ...while consuming current
        if (ii + 2 < 16) K1_LOAD(bufA, ii + 2);
        K1_COMPUTE(bufB, ii + 1);
    }

    #pragma unroll
    for (int p = 0; p < 8; p++) {
        float l0 = lo2(acc[0][p]), h0 = hi2(acc[0][p]);
        float l1 = lo2(acc[1][p]), h1 = hi2(acc[1][p]);
        l0 = l0 >= 0.f ? l0 : 0.2f * l0;
        h0 = h0 >= 0.f ? h0 : 0.2f * h0;
        l1 = l1 >= 0.f ? l1 : 0.2f * l1;
        h1 = h1 >= 0.f ? h1 : 0.2f * h1;
        *(float2*)&sC[2 * p][2 * tid]     = make_float2(l0, l1);
        *(float2*)&sC[2 * p + 1][2 * tid] = make_float2(h0, h1);
    }
    __syncthreads();

    if (tid < 64) {
        int d = tid >> 4, b = tid & 15;
        float s0 = 0.f, s1 = 0.f, s2 = 0.f;
        const float* row = &sC[b][d * 128];
        #pragma unroll 4
        for (int f = 0; f < 128; f++) {
            float cv = row[f];
            s0 = fmaf(cv, sWl[f * 3 + 0], s0);
            s1 = fmaf(cv, sWl[f * 3 + 1], s1);
            s2 = fmaf(cv, sWl[f * 3 + 2], s2);
        }
        const float* rp = &g_root[(b * NNODE + n) * 3];
        float x0 = s0 + rp[0], x1 = s1 + rp[1], x2 = s2 + rp[2];
        float hxx = 0.5f * (x0 * x0 + x1 * x1 + x2 * x2);
        int dglob = jt * 4 + d;
        g_x[b * NPTS + n * DEG + dglob] = make_float4(x0, x1, x2, hxx);
    }
}

// ============================================================
// K2: EXACT R13 version (node-bound pruned kNN, serial prepass —
// the configuration measured inside the 75.9us total).
// ============================================================
__device__ __forceinline__ void topk_ins(float v, int m, float* val, int* idx) {
    float cv = v; int ci = m;
    #pragma unroll
    for (int s = 0; s < KNN; s++) {
        bool gt = (cv > val[s]) || (cv == val[s] && ci < idx[s]);
        float ov = val[s]; int oi = idx[s];
        val[s] = gt ? cv : ov;
        idx[s] = gt ? ci : oi;
        cv = gt ? ov : cv;
        ci = gt ? oi : ci;
    }
}

__global__ __launch_bounds__(64) void k2_knn(const float* __restrict__ bias,
                                             float* __restrict__ out) {
    const int b    = blockIdx.x >> 5;    // 16 batches x 32 nodes (chunks of 64)
    const int chnk = blockIdx.x & 31;
    const int tid  = threadIdx.x;

    __shared__ __align__(16) float sX[NPTS], sY[NPTS], sZ[NPTS], sW[NPTS];
    __shared__ float scx[NNODE], scy[NNODE], scz[NNODE], srad[NNODE];
    __shared__ float sce[18], sbe[3];
    #pragma unroll
    for (int q = 0; q < NPTS / 64; q++) {
        int i = q * 64 + tid;
        float4 v = g_x[b * NPTS + i];
        sX[i] = v.x; sY[i] = v.y; sZ[i] = v.z; sW[i] = -v.w;
    }
    if (tid < 18) sce[tid] = g_ceff[tid];
    if (tid < 3)  sbe[tid] = g_beff[tid];
    __syncthreads();

    // ---- prepass: centroid + radius per node (lane-staggered) ----
    if (tid < NNODE) {
        float cx = 0.f, cy = 0.f, cz = 0.f;
        #pragma unroll 4
        for (int j = 0; j < DEG; j++) {
            int i = tid * DEG + ((j + tid) & 63);
            cx += sX[i]; cy += sY[i]; cz += sZ[i];
        }
        cx *= (1.f / DEG); cy *= (1.f / DEG); cz *= (1.f / DEG);
        float r2 = 0.f;
        #pragma unroll 4
        for (int j = 0; j < DEG; j++) {
            int i = tid * DEG + ((j + tid) & 63);
            float dx = sX[i] - cx, dy = sY[i] - cy, dz = sZ[i] - cz;
            r2 = fmaxf(r2, dx * dx + dy * dy + dz * dz);
        }
        scx[tid] = cx; scy[tid] = cy; scz[tid] = cz;
        srad[tid] = sqrtf(r2) * 1.0001f + 1e-5f;     // inflated (conservative)
    }
    __syncthreads();

    const int n = chnk * 64 + tid;       // this thread's point
    const float nx = sX[n], ny = sY[n], nz = sZ[n];
    const ull nx2 = splat2(nx), ny2 = splat2(ny), nz2 = splat2(nz);
    const ull c0  = splat2(sW[n]);       // = -0.5*||xn||^2

    float val[KNN]; int idx[KNN];
    #pragma unroll
    for (int k = 0; k < KNN; k++) { val[k] = -3.4e38f; idx[k] = 0x7fffffff; }

    const ulonglong2* pX = (const ulonglong2*)sX;
    const ulonglong2* pY = (const ulonglong2*)sY;
    const ulonglong2* pZ = (const ulonglong2*)sZ;
    const ulonglong2* pW = (const ulonglong2*)sW;

    #define K2_SCAN_GROUP(gg)                                                  \
    {                                                                          \
        const int m0 = (gg) * 8;                                               \
        ulonglong2 cX = pX[2 * (gg)],     cY = pY[2 * (gg)],                   \
                   cZ = pZ[2 * (gg)],     cW = pW[2 * (gg)];                   \
        ulonglong2 dX = pX[2 * (gg) + 1], dY = pY[2 * (gg) + 1],               \
                   dZ = pZ[2 * (gg) + 1], dW = pW[2 * (gg) + 1];               \
        ull t0 = ffma2r(nx2, cX.x, ffma2r(ny2, cY.x, ffma2r(nz2, cZ.x, add2r(c0, cW.x)))); \
        ull t1 = ffma2r(nx2, cX.y, ffma2r(ny2, cY.y, ffma2r(nz2, cZ.y, add2r(c0, cW.y)))); \
        ull t2 = ffma2r(nx2, dX.x, ffma2r(ny2, dY.x, ffma2r(nz2, dZ.x, add2r(c0, dW.x)))); \
        ull t3 = ffma2r(nx2, dX.y, ffma2r(ny2, dY.y, ffma2r(nz2, dZ.y, add2r(c0, dW.y)))); \
        float s0 = lo2(t0), s1 = hi2(t0), s2 = lo2(t1), s3 = hi2(t1);          \
        float s4 = lo2(t2), s5 = hi2(t2), s6 = lo2(t3), s7 = hi2(t3);          \
        float gm = fmaxf(fmaxf(fmaxf(s0, s1), fmaxf(s2, s3)),                  \
                         fmaxf(fmaxf(s4, s5), fmaxf(s6, s7)));                 \
        if (gm >= val[KNN - 1]) {                                              \
            if (s0 >= val[KNN - 1]) topk_ins(s0, m0 + 0, val, idx);            \
            if (s1 >= val[KNN - 1]) topk_ins(s1, m0 + 1, val, idx);            \
            if (s2 >= val[KNN - 1]) topk_ins(s2, m0 + 2, val, idx);            \
            if (s3 >= val[KNN - 1]) topk_ins(s3, m0 + 3, val, idx);            \
            if (s4 >= val[KNN - 1]) topk_ins(s4, m0 + 4, val, idx);            \
            if (s5 >= val[KNN - 1]) topk_ins(s5, m0 + 5, val, idx);            \
            if (s6 >= val[KNN - 1]) topk_ins(s6, m0 + 6, val, idx);            \
            if (s7 >= val[KNN - 1]) topk_ins(s7, m0 + 7, val, idx);            \
        }                                                                      \
    }

    // ---- warm-up: own node's 64 candidates (8 groups) ----
    #pragma unroll 1
    for (int t = 0; t < 8; t++) {
        K2_SCAN_GROUP(chnk * 8 + t);
    }

    // ---- prune: search radius from the 8th-best own-node score ----
    const float tau = val[KNN - 1];                   // = -0.5*d8^2 (<= 0)
    const float srch = sqrtf(fmaxf(-2.f * tau, 0.f)) * 1.0001f + 1e-5f;

    #pragma unroll 1
    for (int mn = 0; mn < NNODE; mn++) {
        if (mn == chnk) continue;
        float dx = nx - scx[mn], dy = ny - scy[mn], dz = nz - scz[mn];
        float d2  = dx * dx + dy * dy + dz * dz;
        float rhs = srad[mn] + srch;
        if (d2 <= rhs * rhs) {                        // node may contain a top-8
            #pragma unroll 1
            for (int t = 0; t < 8; t++) {
                K2_SCAN_GROUP(mn * 8 + t);
            }
        }
    }
    #undef K2_SCAN_GROUP

    float h0 = -3.4e38f, h1 = -3.4e38f, h2 = -3.4e38f;
    #pragma unroll
    for (int k = 0; k < KNN; k++) {
        int m = idx[k];
        float mx = sX[m], my = sY[m], mz = sZ[m];
        float g0f = mx - nx, g1f = my - ny, g2f = mz - nz;
        float u0 = sbe[0] + sce[0]  * g0f + sce[1]  * g1f + sce[2]  * g2f
                          + sce[3]  * nx + sce[4]  * ny + sce[5]  * nz;
        float u1 = sbe[1] + sce[6]  * g0f + sce[7]  * g1f + sce[8]  * g2f
                          + sce[9]  * nx + sce[10] * ny + sce[11] * nz;
        float u2 = sbe[2] + sce[12] * g0f + sce[13] * g1f + sce[14] * g2f
                          + sce[15] * nx + sce[16] * ny + sce[17] * nz;
        h0 = fmaxf(h0, u0); h1 = fmaxf(h1, u1); h2 = fmaxf(h2, u2);
    }

    const int bq = tid * 3;              // bias tiled with period DEG=64; n&63==tid
    float o0 = h0 + bias[bq + 0];
    float o1 = h1 + bias[bq + 1];
    float o2 = h2 + bias[bq + 2];
    o0 = o0 >= 0.f ? o0 : 0.2f * o0;
    o1 = o1 >= 0.f ? o1 : 0.2f * o1;
    o2 = o2 >= 0.f ? o2 : 0.2f * o2;

    float* op = out + (size_t)(b * NPTS + n) * 3;
    op[0] = o0; op[1] = o1; op[2] = o2;
}

// ============================================================
extern "C" void kernel_launch(void* const* d_in, const int* in_sizes, int n_in,
                              void* d_out, int out_size) {
    const float* t0  = (const float*)d_in[0];
    const float* t1  = (const float*)d_in[1];
    const float* t2  = (const float*)d_in[2];
    const float* t3  = (const float*)d_in[3];
    const float* t4  = (const float*)d_in[4];
    const float* t5  = (const float*)d_in[5];
    const float* Wr0 = (const float*)d_in[6];
    const float* Wr1 = (const float*)d_in[7];
    const float* Wr2 = (const float*)d_in[8];
    const float* Wr3 = (const float*)d_in[9];
    const float* Wr4 = (const float*)d_in[10];
    const float* Wr5 = (const float*)d_in[11];
    const float* Wb  = (const float*)d_in[12];
    const float* Wl1 = (const float*)d_in[13];
    const float* Wl2 = (const float*)d_in[14];
    const float* bia = (const float*)d_in[15];
    const float* c1w = (const float*)d_in[16];
    const float* c1b = (const float*)d_in[17];
    const float* c2w = (const float*)d_in[18];
    const float* c2b = (const float*)d_in[19];

    k0_prep<<<641, 256>>>(t0, t1, t2, t3, t4, t5,
                          Wr0, Wr1, Wr2, Wr3, Wr4, Wr5,
                          Wl1, Wl2, c1w, c1b, c2w, c2b);
    k1_branch<<<NNODE * 16, 256>>>(t5, Wb);
    k2_knn<<<BATCH * 32, 64>>>(bia, (float*)d_out);
}

// round 16
// speedup vs baseline: 1.1711x; 1.0846x over previous
#include <cuda_runtime.h>

#define BATCH 16
#define NNODE 32
#define DEG 64
#define KNN 8
#define IN_F 128
#define OUT_F 3
#define NPTS 2048   // NNODE*DEG
#define JCOLS 8192  // DEG*IN_F

typedef unsigned long long ull;

// ---------- device scratch (no allocations allowed) ----------
__device__ float  g_root[BATCH * NNODE * OUT_F];
__device__ float  g_Wl[IN_F * OUT_F];     // collapsed Wl1@Wl2, layout [f*3+o]
__device__ float  g_ceff[OUT_F * 6];      // collapsed c2w@c1w, layout [p*6+c]
__device__ float  g_beff[OUT_F];          // c2w@c1b + c2b
__device__ float4 g_x[BATCH * NPTS];      // (x0,x1,x2, 0.5*||x||^2)

// ---------- packed f32x2 helpers ----------
__device__ __forceinline__ ull splat2(float w) {
    ull r;
    asm("mov.b64 %0, {%1, %1};" : "=l"(r) : "f"(w));
    return r;
}
__device__ __forceinline__ void ffma2(ull& d, ull a, ull b) {
    asm("fma.rn.f32x2 %0, %1, %2, %0;" : "+l"(d) : "l"(a), "l"(b));
}
__device__ __forceinline__ ull ffma2r(ull a, ull b, ull c) {
    ull d;
    asm("fma.rn.f32x2 %0, %1, %2, %3;" : "=l"(d) : "l"(a), "l"(b), "l"(c));
    return d;
}
__device__ __forceinline__ ull add2r(ull a, ull b) {
    ull d;
    asm("add.rn.f32x2 %0, %1, %2;" : "=l"(d) : "l"(a), "l"(b));
    return d;
}
__device__ __forceinline__ float lo2(ull v) {
    return __uint_as_float((unsigned)(v & 0xffffffffu));
}
__device__ __forceinline__ float hi2(ull v) {
    return __uint_as_float((unsigned)(v >> 32));
}

__device__ __forceinline__ float wredsum(float v) {
    #pragma unroll
    for (int o = 16; o > 0; o >>= 1) v += __shfl_xor_sync(0xffffffffu, v, o);
    return v;
}

// ============================================================
// K0: EXACT R15 version (measured 7.6us).
// ============================================================
__global__ __launch_bounds__(256) void k0_prep(
        const float* __restrict__ t0, const float* __restrict__ t1,
        const float* __restrict__ t2, const float* __restrict__ t3,
        const float* __restrict__ t4, const float* __restrict__ t5,
        const float* __restrict__ Wr0, const float* __restrict__ Wr1,
        const float* __restrict__ Wr2, const float* __restrict__ Wr3,
        const float* __restrict__ Wr4, const float* __restrict__ Wr5,
        const float* __restrict__ Wl1, const float* __restrict__ Wl2,
        const float* __restrict__ c1w, const float* __restrict__ c1b,
        const float* __restrict__ c2w, const float* __restrict__ c2b) {
    const int bid = blockIdx.x;
    const int tid = threadIdx.x;
    const int w   = tid >> 5, lane = tid & 31;
    __shared__ float red[8][3];

    if (bid < 512) {
        const int b = bid >> 5, n = bid & 31;
        float s0 = 0.f, s1 = 0.f, s2 = 0.f;
        #pragma unroll
        for (int it = 0; it < 5; it++) {
            int idx = tid + it * 256;
            if (idx < 1120) {
                float v; const float* wp;
                if (idx < 96) {
                    v = t0[b * 96 + idx];                           wp = Wr0 + idx * 3;
                } else if (idx < 352) {
                    int i = idx - 96;
                    v = t1[(b * 2  + (n >> 4)) * 256 + i];          wp = Wr1 + i * 3;
                } else if (idx < 608) {
                    int i = idx - 352;
                    v = t2[(b * 4  + (n >> 3)) * 256 + i];          wp = Wr2 + i * 3;
                } else if (idx < 864) {
                    int i = idx - 608;
                    v = t3[(b * 8  + (n >> 2)) * 256 + i];          wp = Wr3 + i * 3;
                } else if (idx < 992) {
                    int i = idx - 864;
                    v = t4[(b * 16 + (n >> 1)) * 128 + i];          wp = Wr4 + i * 3;
                } else {
                    int i = idx - 992;
                    v = t5[(b * 32 +  n      ) * 128 + i];          wp = Wr5 + i * 3;
                }
                s0 = fmaf(v, wp[0], s0); s1 = fmaf(v, wp[1], s1); s2 = fmaf(v, wp[2], s2);
            }
        }
        s0 = wredsum(s0); s1 = wredsum(s1); s2 = wredsum(s2);
        if (lane == 0) { red[w][0] = s0; red[w][1] = s1; red[w][2] = s2; }
        __syncthreads();
        if (tid < 3) {
            float t = 0.f;
            #pragma unroll
            for (int q = 0; q < 8; q++) t += red[q][tid];
            g_root[(b * NNODE + n) * 3 + tid] = t;
        }
    } else if (bid < 640) {
        const int f = bid - 512;
        float s0 = 0.f, s1 = 0.f, s2 = 0.f;
        #pragma unroll
        for (int it = 0; it < 5; it++) {
            int tt = tid + it * 256;   // 1280 = 5*256 exactly
            float v = Wl1[f * 1280 + tt];
            s0 = fmaf(v, Wl2[tt * 3 + 0], s0);
            s1 = fmaf(v, Wl2[tt * 3 + 1], s1);
            s2 = fmaf(v, Wl2[tt * 3 + 2], s2);
        }
        s0 = wredsum(s0); s1 = wredsum(s1); s2 = wredsum(s2);
        if (lane == 0) { red[w][0] = s0; red[w][1] = s1; red[w][2] = s2; }
        __syncthreads();
        if (tid < 3) {
            float t = 0.f;
            #pragma unroll
            for (int q = 0; q < 8; q++) t += red[q][tid];
            g_Wl[f * 3 + tid] = t;
        }
    } else {
        if (tid < 18) {
            int p = tid / 6, c = tid % 6;
            float s = 0.f;
            for (int o = 0; o < 64; o++) s = fmaf(c2w[p * 64 + o], c1w[o * 6 + c], s);
            g_ceff[tid] = s;
        } else if (tid < 21) {
            int p = tid - 18;
            float s = c2b[p];
            for (int o = 0; o < 64; o++) s = fmaf(c2w[p * 64 + o], c1b[o], s);
            g_beff[p] = s;
        }
    }
}

// ============================================================
// K1: 128 threads x 4 cols/thread (acc[4][8]) + R11 dist-1 pipeline.
// Same 64B of sa per i now feeds 32 FFMA2 (2 B/FFMA2, was 4):
// LDS crossbar demand halves from 56.6k to 28.3k cyc/SM, reaching
// parity with the 28.4k fma floor instead of 2x above it.
// W loads are float4 (one LDG.128 per i), window-4 double buffer.
// ============================================================
#define K1_LOAD4(buf, wi)                                             \
    {                                                                 \
        _Pragma("unroll")                                             \
        for (int k = 0; k < 4; k++)                                   \
            buf[k] = __ldcs(wptr + (size_t)((wi) * 4 + k) * (JCOLS / 4)); \
    }

#define K1_COMPUTE4(buf, wi)                                          \
    {                                                                 \
        _Pragma("unroll")                                             \
        for (int k = 0; k < 4; k++) {                                 \
            ull w0 = splat2(buf[k].x), w1 = splat2(buf[k].y);         \
            ull w2 = splat2(buf[k].z), w3 = splat2(buf[k].w);         \
            const ulonglong2* sap =                                   \
                (const ulonglong2*)(sa + ((wi) * 4 + k) * 8);         \
            _Pragma("unroll")                                         \
            for (int q = 0; q < 4; q++) {                             \
                ulonglong2 ap = sap[q];                               \
                ffma2(acc[0][2 * q],     ap.x, w0);                   \
                ffma2(acc[1][2 * q],     ap.x, w1);                   \
                ffma2(acc[2][2 * q],     ap.x, w2);                   \
                ffma2(acc[3][2 * q],     ap.x, w3);                   \
                ffma2(acc[0][2 * q + 1], ap.y, w0);                   \
                ffma2(acc[1][2 * q + 1], ap.y, w1);                   \
                ffma2(acc[2][2 * q + 1], ap.y, w2);                   \
                ffma2(acc[3][2 * q + 1], ap.y, w3);                   \
            }                                                         \
        }                                                             \
    }

__global__ __launch_bounds__(128) void k1_branch(const float* __restrict__ t5,
                                                 const float* __restrict__ Wb) {
    const int n   = blockIdx.x >> 4;
    const int jt  = blockIdx.x & 15;
    const int j0  = jt * 512;
    const int tid = threadIdx.x;

    __shared__ __align__(16) ull sa[IN_F * 8];  // [i][bpair]
    __shared__ __align__(16) float sC[16][516];
    __shared__ float sWl[IN_F * OUT_F];

    {
        int i = tid;  // 128 threads == IN_F
        #pragma unroll
        for (int p = 0; p < 8; p++) {
            float a0 = t5[((2 * p)     * NNODE + n) * IN_F + i];
            float a1 = t5[((2 * p + 1) * NNODE + n) * IN_F + i];
            sa[i * 8 + p] = ((ull)__float_as_uint(a1) << 32)
                          | (ull)__float_as_uint(a0);
        }
        for (int q = tid; q < IN_F * OUT_F; q += 128) sWl[q] = g_Wl[q];
    }
    __syncthreads();

    ull acc[4][8];
    #pragma unroll
    for (int c = 0; c < 4; c++)
        #pragma unroll
        for (int p = 0; p < 8; p++) acc[c][p] = 0ull;

    const float4* wptr =
        (const float4*)(Wb + (size_t)n * IN_F * JCOLS + j0 + 4 * tid);

    float4 bufA[4], bufB[4];
    K1_LOAD4(bufA, 0);                   // prologue: window 0 in flight

    #pragma unroll 1
    for (int ii = 0; ii < 32; ii += 2) {
        K1_LOAD4(bufB, ii + 1);          // next window in flight...
        K1_COMPUTE4(bufA, ii);           // ...while consuming current
        if (ii + 2 < 32) K1_LOAD4(bufA, ii + 2);
        K1_COMPUTE4(bufB, ii + 1);
    }

    // leaky -> sC (float4 stores per batch row)
    #pragma unroll
    for (int p = 0; p < 8; p++) {
        float lo[4], hi[4];
        #pragma unroll
        for (int c = 0; c < 4; c++) {
            float l = lo2(acc[c][p]), h = hi2(acc[c][p]);
            lo[c] = l >= 0.f ? l : 0.2f * l;
            hi[c] = h >= 0.f ? h : 0.2f * h;
        }
        *(float4*)&sC[2 * p][4 * tid]     = make_float4(lo[0], lo[1], lo[2], lo[3]);
        *(float4*)&sC[2 * p + 1][4 * tid] = make_float4(hi[0], hi[1], hi[2], hi[3]);
    }
    __syncthreads();

    if (tid < 64) {
        int d = tid >> 4, b = tid & 15;
        float s0 = 0.f, s1 = 0.f, s2 = 0.f;
        const float* row = &sC[b][d * 128];
        #pragma unroll 4
        for (int f = 0; f < 128; f++) {
            float cv = row[f];
            s0 = fmaf(cv, sWl[f * 3 + 0], s0);
            s1 = fmaf(cv, sWl[f * 3 + 1], s1);
            s2 = fmaf(cv, sWl[f * 3 + 2], s2);
        }
        const float* rp = &g_root[(b * NNODE + n) * 3];
        float x0 = s0 + rp[0], x1 = s1 + rp[1], x2 = s2 + rp[2];
        float hxx = 0.5f * (x0 * x0 + x1 * x1 + x2 * x2);
        int dglob = jt * 4 + d;
        g_x[b * NPTS + n * DEG + dglob] = make_float4(x0, x1, x2, hxx);
    }
}

// ============================================================
// K2: EXACT R13 version (node-bound pruned kNN; measured in the
// 75.9/73.9us totals).
// ============================================================
__device__ __forceinline__ void topk_ins(float v, int m, float* val, int* idx) {
    float cv = v; int ci = m;
    #pragma unroll
    for (int s = 0; s < KNN; s++) {
        bool gt = (cv > val[s]) || (cv == val[s] && ci < idx[s]);
        float ov = val[s]; int oi = idx[s];
        val[s] = gt ? cv : ov;
        idx[s] = gt ? ci : oi;
        cv = gt ? ov : cv;
        ci = gt ? oi : ci;
    }
}

__global__ __launch_bounds__(64) void k2_knn(const float* __restrict__ bias,
                                             float* __restrict__ out) {
    const int b    = blockIdx.x >> 5;    // 16 batches x 32 nodes (chunks of 64)
    const int chnk = blockIdx.x & 31;
    const int tid  = threadIdx.x;

    __shared__ __align__(16) float sX[NPTS], sY[NPTS], sZ[NPTS], sW[NPTS];
    __shared__ float scx[NNODE], scy[NNODE], scz[NNODE], srad[NNODE];
    __shared__ float sce[18], sbe[3];
    #pragma unroll
    for (int q = 0; q < NPTS / 64; q++) {
        int i = q * 64 + tid;
        float4 v = g_x[b * NPTS + i];
        sX[i] = v.x; sY[i] = v.y; sZ[i] = v.z; sW[i] = -v.w;
    }
    if (tid < 18) sce[tid] = g_ceff[tid];
    if (tid < 3)  sbe[tid] = g_beff[tid];
    __syncthreads();

    // ---- prepass: centroid + radius per node (lane-staggered) ----
    if (tid < NNODE) {
        float cx = 0.f, cy = 0.f, cz = 0.f;
        #pragma unroll 4
        for (int j = 0; j < DEG; j++) {
            int i = tid * DEG + ((j + tid) & 63);
            cx += sX[i]; cy += sY[i]; cz += sZ[i];
        }
        cx *= (1.f / DEG); cy *= (1.f / DEG); cz *= (1.f / DEG);
        float r2 = 0.f;
        #pragma unroll 4
        for (int j = 0; j < DEG; j++) {
            int i = tid * DEG + ((j + tid) & 63);
            float dx = sX[i] - cx, dy = sY[i] - cy, dz = sZ[i] - cz;
            r2 = fmaxf(r2, dx * dx + dy * dy + dz * dz);
        }
        scx[tid] = cx; scy[tid] = cy; scz[tid] = cz;
        srad[tid] = sqrtf(r2) * 1.0001f + 1e-5f;     // inflated (conservative)
    }
    __syncthreads();

    const int n = chnk * 64 + tid;       // this thread's point
    const float nx = sX[n], ny = sY[n], nz = sZ[n];
    const ull nx2 = splat2(nx), ny2 = splat2(ny), nz2 = splat2(nz);
    const ull c0  = splat2(sW[n]);       // = -0.5*||xn||^2

    float val[KNN]; int idx[KNN];
    #pragma unroll
    for (int k = 0; k < KNN; k++) { val[k] = -3.4e38f; idx[k] = 0x7fffffff; }

    const ulonglong2* pX = (const ulonglong2*)sX;
    const ulonglong2* pY = (const ulonglong2*)sY;
    const ulonglong2* pZ = (const ulonglong2*)sZ;
    const ulonglong2* pW = (const ulonglong2*)sW;

    #define K2_SCAN_GROUP(gg)                                                  \
    {                                                                          \
        const int m0 = (gg) * 8;                                               \
        ulonglong2 cX = pX[2 * (gg)],     cY = pY[2 * (gg)],                   \
                   cZ = pZ[2 * (gg)],     cW = pW[2 * (gg)];                   \
        ulonglong2 dX = pX[2 * (gg) + 1], dY = pY[2 * (gg) + 1],               \
                   dZ = pZ[2 * (gg) + 1], dW = pW[2 * (gg) + 1];               \
        ull t0 = ffma2r(nx2, cX.x, ffma2r(ny2, cY.x, ffma2r(nz2, cZ.x, add2r(c0, cW.x)))); \
        ull t1 = ffma2r(nx2, cX.y, ffma2r(ny2, cY.y, ffma2r(nz2, cZ.y, add2r(c0, cW.y)))); \
        ull t2 = ffma2r(nx2, dX.x, ffma2r(ny2, dY.x, ffma2r(nz2, dZ.x, add2r(c0, dW.x)))); \
        ull t3 = ffma2r(nx2, dX.y, ffma2r(ny2, dY.y, ffma2r(nz2, dZ.y, add2r(c0, dW.y)))); \
        float s0 = lo2(t0), s1 = hi2(t0), s2 = lo2(t1), s3 = hi2(t1);          \
        float s4 = lo2(t2), s5 = hi2(t2), s6 = lo2(t3), s7 = hi2(t3);          \
        float gm = fmaxf(fmaxf(fmaxf(s0, s1), fmaxf(s2, s3)),                  \
                         fmaxf(fmaxf(s4, s5), fmaxf(s6, s7)));                 \
        if (gm >= val[KNN - 1]) {                                              \
            if (s0 >= val[KNN - 1]) topk_ins(s0, m0 + 0, val, idx);            \
            if (s1 >= val[KNN - 1]) topk_ins(s1, m0 + 1, val, idx);            \
            if (s2 >= val[KNN - 1]) topk_ins(s2, m0 + 2, val, idx);            \
            if (s3 >= val[KNN - 1]) topk_ins(s3, m0 + 3, val, idx);            \
            if (s4 >= val[KNN - 1]) topk_ins(s4, m0 + 4, val, idx);            \
            if (s5 >= val[KNN - 1]) topk_ins(s5, m0 + 5, val, idx);            \
            if (s6 >= val[KNN - 1]) topk_ins(s6, m0 + 6, val, idx);            \
            if (s7 >= val[KNN - 1]) topk_ins(s7, m0 + 7, val, idx);            \
        }                                                                      \
    }

    // ---- warm-up: own node's 64 candidates (8 groups) ----
    #pragma unroll 1
    for (int t = 0; t < 8; t++) {
        K2_SCAN_GROUP(chnk * 8 + t);
    }

    // ---- prune: search radius from the 8th-best own-node score ----
    const float tau = val[KNN - 1];                   // = -0.5*d8^2 (<= 0)
    const float srch = sqrtf(fmaxf(-2.f * tau, 0.f)) * 1.0001f + 1e-5f;

    #pragma unroll 1
    for (int mn = 0; mn < NNODE; mn++) {
        if (mn == chnk) continue;
        float dx = nx - scx[mn], dy = ny - scy[mn], dz = nz - scz[mn];
        float d2  = dx * dx + dy * dy + dz * dz;
        float rhs = srad[mn] + srch;
        if (d2 <= rhs * rhs) {                        // node may contain a top-8
            #pragma unroll 1
            for (int t = 0; t < 8; t++) {
                K2_SCAN_GROUP(mn * 8 + t);
            }
        }
    }
    #undef K2_SCAN_GROUP

    float h0 = -3.4e38f, h1 = -3.4e38f, h2 = -3.4e38f;
    #pragma unroll
    for (int k = 0; k < KNN; k++) {
        int m = idx[k];
        float mx = sX[m], my = sY[m], mz = sZ[m];
        float g0f = mx - nx, g1f = my - ny, g2f = mz - nz;
        float u0 = sbe[0] + sce[0]  * g0f + sce[1]  * g1f + sce[2]  * g2f
                          + sce[3]  * nx + sce[4]  * ny + sce[5]  * nz;
        float u1 = sbe[1] + sce[6]  * g0f + sce[7]  * g1f + sce[8]  * g2f
                          + sce[9]  * nx + sce[10] * ny + sce[11] * nz;
        float u2 = sbe[2] + sce[12] * g0f + sce[13] * g1f + sce[14] * g2f
                          + sce[15] * nx + sce[16] * ny + sce[17] * nz;
        h0 = fmaxf(h0, u0); h1 = fmaxf(h1, u1); h2 = fmaxf(h2, u2);
    }

    const int bq = tid * 3;              // bias tiled with period DEG=64; n&63==tid
    float o0 = h0 + bias[bq + 0];
    float o1 = h1 + bias[bq + 1];
    float o2 = h2 + bias[bq + 2];
    o0 = o0 >= 0.f ? o0 : 0.2f * o0;
    o1 = o1 >= 0.f ? o1 : 0.2f * o1;
    o2 = o2 >= 0.f ? o2 : 0.2f * o2;

    float* op = out + (size_t)(b * NPTS + n) * 3;
    op[0] = o0; op[1] = o1; op[2] = o2;
}

// ============================================================
extern "C" void kernel_launch(void* const* d_in, const int* in_sizes, int n_in,
                              void* d_out, int out_size) {
    const float* t0  = (const float*)d_in[0];
    const float* t1  = (const float*)d_in[1];
    const float* t2  = (const float*)d_in[2];
    const float* t3  = (const float*)d_in[3];
    const float* t4  = (const float*)d_in[4];
    const float* t5  = (const float*)d_in[5];
    const float* Wr0 = (const float*)d_in[6];
    const float* Wr1 = (const float*)d_in[7];
    const float* Wr2 = (const float*)d_in[8];
    const float* Wr3 = (const float*)d_in[9];
    const float* Wr4 = (const float*)d_in[10];
    const float* Wr5 = (const float*)d_in[11];
    const float* Wb  = (const float*)d_in[12];
    const float* Wl1 = (const float*)d_in[13];
    const float* Wl2 = (const float*)d_in[14];
    const float* bia = (const float*)d_in[15];
    const float* c1w = (const float*)d_in[16];
    const float* c1b = (const float*)d_in[17];
    const float* c2w = (const float*)d_in[18];
    const float* c2b = (const float*)d_in[19];

    k0_prep<<<641, 256>>>(t0, t1, t2, t3, t4, t5,
                          Wr0, Wr1, Wr2, Wr3, Wr4, Wr5,
                          Wl1, Wl2, c1w, c1b, c2w, c2b);
    k1_branch<<<NNODE * 16, 128>>>(t5, Wb);
    k2_knn<<<BATCH * 32, 64>>>(bia, (float*)d_out);
}